// round 7
// baseline (speedup 1.0000x reference)
#include <cuda_runtime.h>
#include <cuda_bf16.h>
#include <cuda_fp16.h>
#include <cstdint>

#define NN 50000
#define NE 800000
#define DD 128

// ---------------- scratch (static device globals; no allocation) ----------------
__device__ int   g_is64;
__device__ int   g_total;
__device__ int   g_deg[NN];
__device__ int   g_off[NN];
__device__ int   g_cur[NN];
__device__ float g_invdeg[NN];
__device__ int   g_col[NE];
__device__ float g_agg[(size_t)NN * DD];
__device__ float g_h1 [(size_t)NN * DD];
__device__ float g_h2 [(size_t)NN * DD];
__device__ __half2 g_f16[(size_t)NN * (DD / 2)];   // fp16 mirror of current features

__device__ __forceinline__ const float* sel_in(int sel, const float* x) {
    return sel == 0 ? x : (sel == 1 ? (const float*)g_h1 : (const float*)g_h2);
}
__device__ __forceinline__ int get_src(const int* __restrict__ ei, int e) {
    return g_is64 ? ei[2 * e] : ei[e];
}
__device__ __forceinline__ int get_dst(const int* __restrict__ ei, int e) {
    return g_is64 ? ei[2 * NE + 2 * e] : ei[NE + e];
}

// Split a float pair into bf16-hi pair (packed b32) and bf16-lo residual pair.
__device__ __forceinline__ uint32_t pack_hi_lo(float a, float b, uint32_t* lo) {
    __nv_bfloat16 ha = __float2bfloat16_rn(a);
    __nv_bfloat16 hb = __float2bfloat16_rn(b);
    __nv_bfloat16 la = __float2bfloat16_rn(a - __bfloat162float(ha));
    __nv_bfloat16 lb = __float2bfloat16_rn(b - __bfloat162float(hb));
    *lo = ((uint32_t)__bfloat16_as_ushort(lb) << 16) | __bfloat16_as_ushort(la);
    return ((uint32_t)__bfloat16_as_ushort(hb) << 16) | __bfloat16_as_ushort(ha);
}

__device__ __forceinline__ void mma16816(float* d, const uint32_t* a, uint32_t b0, uint32_t b1) {
    asm volatile(
        "mma.sync.aligned.m16n8k16.row.col.f32.bf16.bf16.f32 "
        "{%0,%1,%2,%3}, {%4,%5,%6,%7}, {%8,%9}, {%0,%1,%2,%3};"
        : "+f"(d[0]), "+f"(d[1]), "+f"(d[2]), "+f"(d[3])
        : "r"(a[0]), "r"(a[1]), "r"(a[2]), "r"(a[3]), "r"(b0), "r"(b1));
}

// ---------------- dtype detection ----------------
__global__ void k_detect(const int* __restrict__ ei) {
    if (threadIdx.x == 0 && blockIdx.x == 0) {
        int acc = 0;
        for (int i = 1; i < 512; i += 2) acc |= ei[i];
        g_is64 = (acc == 0) ? 1 : 0;
    }
}

// ---------------- CSR build ----------------
__global__ void k_zero_deg() {
    int i = blockIdx.x * blockDim.x + threadIdx.x;
    if (i < NN) g_deg[i] = 0;
    if (i == 0) g_total = 0;
}
__global__ void k_hist(const int* __restrict__ ei) {
    int e = blockIdx.x * blockDim.x + threadIdx.x;
    if (e < NE) {
        int d = get_dst(ei, e);
        if ((unsigned)d < NN) atomicAdd(&g_deg[d], 1);
    }
}
__global__ __launch_bounds__(256) void k_alloc() {
    __shared__ int warp_sums[8];
    __shared__ int block_base;
    int i = blockIdx.x * 256 + threadIdx.x;
    int lane = threadIdx.x & 31;
    int wid  = threadIdx.x >> 5;
    int d = (i < NN) ? g_deg[i] : 0;
    int sc = d;
#pragma unroll
    for (int o = 1; o < 32; o <<= 1) {
        int v = __shfl_up_sync(0xffffffffu, sc, o);
        if (lane >= o) sc += v;
    }
    if (lane == 31) warp_sums[wid] = sc;
    __syncthreads();
    if (wid == 0) {
        int ws = (lane < 8) ? warp_sums[lane] : 0;
#pragma unroll
        for (int o = 1; o < 8; o <<= 1) {
            int v = __shfl_up_sync(0xffffffffu, ws, o);
            if (lane >= o) ws += v;
        }
        if (lane < 8) warp_sums[lane] = ws;
        if (lane == 7) block_base = atomicAdd(&g_total, ws);
    }
    __syncthreads();
    if (i < NN) {
        int excl = sc - d + (wid > 0 ? warp_sums[wid - 1] : 0) + block_base;
        g_off[i] = excl;
        g_cur[i] = excl;
        g_invdeg[i] = 1.0f / (float)(d > 0 ? d : 1);
    }
}
__global__ void k_fill(const int* __restrict__ ei) {
    int e = blockIdx.x * blockDim.x + threadIdx.x;
    if (e < NE) {
        int d = get_dst(ei, e);
        int s = get_src(ei, e);
        if ((unsigned)d < NN && (unsigned)s < NN) {
            int p = atomicAdd(&g_cur[d], 1);
            g_col[p] = s;
        }
    }
}

// ---------------- fp32 -> fp16 mirror of x ----------------
__global__ void k_cvt(const float* __restrict__ x) {
    int i = blockIdx.x * blockDim.x + threadIdx.x;
    if (i < NN * (DD / 2)) {
        float2 f = ((const float2*)x)[i];
        g_f16[i] = __floats2half2_rn(f.x, f.y);
    }
}

// ---------------- mean aggregation from fp16 mirror: one warp per node --------
// Lane handles feature cols [lane*4, lane*4+4) = 2 half2 = one 8B load per edge.
__global__ __launch_bounds__(256) void k_agg16() {
    int node = (blockIdx.x * blockDim.x + threadIdx.x) >> 5;
    int lane = threadIdx.x & 31;
    if (node >= NN) return;
    int beg = g_off[node];
    int end = beg + g_deg[node];
    float a0 = 0.f, a1 = 0.f, a2 = 0.f, a3 = 0.f;
    for (int e = beg; e < end; ++e) {
        int s = g_col[e];
        uint2 raw = *(const uint2*)(g_f16 + (size_t)s * (DD / 2) + lane * 2);
        float2 f0 = __half22float2(*(__half2*)&raw.x);
        float2 f1 = __half22float2(*(__half2*)&raw.y);
        a0 += f0.x; a1 += f0.y; a2 += f1.x; a3 += f1.y;
    }
    float inv = g_invdeg[node];
    ((float4*)(g_agg + (size_t)node * DD))[lane] =
        make_float4(a0 * inv, a1 * inv, a2 * inv, a3 * inv);
}

// ---------------- HMMA bf16-split GEMM ----------------------------------------
// out = agg @ Wl^T + h @ Wr^T + b (+relu); split precision via 3 bf16 products.
// Also writes fp16 mirror of the output when write16 (layers 1,2).
#define KPAD 20   // b32 per SMEM row (32 bf16 data + 8 pad)

__global__ __launch_bounds__(256) void k_gemm_mma(int in_sel, const float* __restrict__ x,
                                                  const float* __restrict__ Wl,
                                                  const float* __restrict__ bl,
                                                  const float* __restrict__ Wr,
                                                  int out_sel, float* __restrict__ ext_out,
                                                  int relu) {
    __shared__ uint32_t AsH[128 * KPAD];
    __shared__ uint32_t AsL[128 * KPAD];
    __shared__ uint32_t BsH[128 * KPAD];
    __shared__ uint32_t BsL[128 * KPAD];

    const int tid  = threadIdx.x;
    const int wid  = tid >> 5;
    const int lane = tid & 31;
    const int warpM = wid >> 1;       // 0..3
    const int warpN = wid & 1;        // 0..1
    const int blockM = blockIdx.x * 128;
    const int write16 = (out_sel != 0);

    const float* A1 = sel_in(in_sel, x);
    float* outp = out_sel == 0 ? ext_out : (out_sel == 1 ? (float*)g_h1 : (float*)g_h2);

    float acc[2][8][4];
#pragma unroll
    for (int mt = 0; mt < 2; ++mt)
#pragma unroll
        for (int nt = 0; nt < 8; ++nt)
#pragma unroll
            for (int c = 0; c < 4; ++c) acc[mt][nt][c] = 0.f;

    const int ldRow = tid >> 1;
    const int ldK   = (tid & 1) << 4;   // 0 or 16

    for (int kc = 0; kc < 8; ++kc) {
        const float* A = (kc < 4) ? (const float*)g_agg : A1;
        const float* W = (kc < 4) ? Wl : Wr;
        const int kb = (kc & 3) * 32;

        {
            int rg = blockM + ldRow;
            const float* src = A + (size_t)((rg < NN) ? rg : 0) * DD + kb + ldK;
            uint32_t* dh = &AsH[ldRow * KPAD + (ldK >> 1)];
            uint32_t* dl = &AsL[ldRow * KPAD + (ldK >> 1)];
#pragma unroll
            for (int i = 0; i < 8; ++i) {
                float2 f = ((const float2*)src)[i];
                uint32_t lo;
                uint32_t hi = pack_hi_lo(f.x, f.y, &lo);
                dh[i] = hi;
                dl[i] = lo;
            }
        }
        {
            const float* src = W + (size_t)ldRow * DD + kb + ldK;
            uint32_t* dh = &BsH[ldRow * KPAD + (ldK >> 1)];
            uint32_t* dl = &BsL[ldRow * KPAD + (ldK >> 1)];
#pragma unroll
            for (int i = 0; i < 8; ++i) {
                float2 f = ((const float2*)src)[i];
                uint32_t lo;
                uint32_t hi = pack_hi_lo(f.x, f.y, &lo);
                dh[i] = hi;
                dl[i] = lo;
            }
        }
        __syncthreads();

#pragma unroll
        for (int ks = 0; ks < 2; ++ks) {
            const int kw = ks * 8;
            uint32_t ah[2][4], al[2][4];
#pragma unroll
            for (int mt = 0; mt < 2; ++mt) {
                int row = warpM * 32 + mt * 16 + (lane >> 2);
                int base = row * KPAD + kw + (lane & 3);
                ah[mt][0] = AsH[base];
                ah[mt][1] = AsH[base + 8 * KPAD];
                ah[mt][2] = AsH[base + 4];
                ah[mt][3] = AsH[base + 8 * KPAD + 4];
                al[mt][0] = AsL[base];
                al[mt][1] = AsL[base + 8 * KPAD];
                al[mt][2] = AsL[base + 4];
                al[mt][3] = AsL[base + 8 * KPAD + 4];
            }
#pragma unroll
            for (int nt = 0; nt < 8; ++nt) {
                int n = warpN * 64 + nt * 8 + (lane >> 2);
                int bbase = n * KPAD + kw + (lane & 3);
                uint32_t bh0 = BsH[bbase], bh1 = BsH[bbase + 4];
                uint32_t bl0 = BsL[bbase], bl1 = BsL[bbase + 4];
#pragma unroll
                for (int mt = 0; mt < 2; ++mt) {
                    mma16816(acc[mt][nt], ah[mt], bh0, bh1);   // Ah*Bh
                    mma16816(acc[mt][nt], ah[mt], bl0, bl1);   // Ah*Bl
                    mma16816(acc[mt][nt], al[mt], bh0, bh1);   // Al*Bh
                }
            }
        }
        __syncthreads();
    }

    // ---- epilogue: bias (+relu), fp32 stores + fp16 mirror ----
#pragma unroll
    for (int nt = 0; nt < 8; ++nt) {
        int col = warpN * 64 + nt * 8 + (lane & 3) * 2;
        float2 bb = *(const float2*)(bl + col);
#pragma unroll
        for (int mt = 0; mt < 2; ++mt) {
            int row = blockM + warpM * 32 + mt * 16 + (lane >> 2);
            float* d = acc[mt][nt];
            float2 o0 = make_float2(d[0] + bb.x, d[1] + bb.y);
            float2 o1 = make_float2(d[2] + bb.x, d[3] + bb.y);
            if (relu) {
                o0.x = fmaxf(o0.x, 0.f); o0.y = fmaxf(o0.y, 0.f);
                o1.x = fmaxf(o1.x, 0.f); o1.y = fmaxf(o1.y, 0.f);
            }
            if (row < NN) {
                *(float2*)(outp + (size_t)row * DD + col) = o0;
                if (write16)
                    g_f16[(size_t)row * (DD / 2) + (col >> 1)] = __floats2half2_rn(o0.x, o0.y);
            }
            if (row + 8 < NN) {
                *(float2*)(outp + (size_t)(row + 8) * DD + col) = o1;
                if (write16)
                    g_f16[(size_t)(row + 8) * (DD / 2) + (col >> 1)] = __floats2half2_rn(o1.x, o1.y);
            }
        }
    }
}

// ---------------- launch (kernel launches ONLY; graph-capture safe) ----------
extern "C" void kernel_launch(void* const* d_in, const int* in_sizes, int n_in,
                              void* d_out, int out_size) {
    const float* x  = (const float*)d_in[0];
    const int*   ei = (const int*)d_in[1];
    const float* Wl1 = (const float*)d_in[2];
    const float* bl1 = (const float*)d_in[3];
    const float* Wr1 = (const float*)d_in[4];
    const float* Wl2 = (const float*)d_in[5];
    const float* bl2 = (const float*)d_in[6];
    const float* Wr2 = (const float*)d_in[7];
    const float* Wl3 = (const float*)d_in[8];
    const float* bl3 = (const float*)d_in[9];
    const float* Wr3 = (const float*)d_in[10];
    float* out = (float*)d_out;

    k_detect<<<1, 32>>>(ei);
    k_zero_deg<<<(NN + 255) / 256, 256>>>();
    k_hist<<<(NE + 255) / 256, 256>>>(ei);
    k_alloc<<<(NN + 255) / 256, 256>>>();
    k_fill<<<(NE + 255) / 256, 256>>>(ei);
    k_cvt<<<(NN * (DD / 2) + 255) / 256, 256>>>(x);

    const int aggGrid  = (NN + 7) / 8;
    const int gemmGrid = (NN + 127) / 128;   // 391

    // Layer 1 (+ReLU): agg(f16(x)) -> g_agg; gemm -> g_h1 (+f16 mirror)
    k_agg16<<<aggGrid, 256>>>();
    k_gemm_mma<<<gemmGrid, 256>>>(0, x, Wl1, bl1, Wr1, 1, out, 1);
    // Layer 2
    k_agg16<<<aggGrid, 256>>>();
    k_gemm_mma<<<gemmGrid, 256>>>(1, x, Wl2, bl2, Wr2, 2, out, 0);
    // Layer 3 -> d_out (no mirror)
    k_agg16<<<aggGrid, 256>>>();
    k_gemm_mma<<<gemmGrid, 256>>>(2, x, Wl3, bl3, Wr3, 0, out, 0);
}

// round 8
// speedup vs baseline: 1.2767x; 1.2767x over previous
#include <cuda_runtime.h>
#include <cuda_bf16.h>
#include <cstdint>

#define NN 50000
#define NE 800000
#define DD 128

// ---------------- scratch (static device globals; no allocation) ----------------
__device__ int   g_is64;
__device__ int   g_total;
__device__ int   g_deg[NN];
__device__ int   g_off[NN];
__device__ int   g_cur[NN];
__device__ float g_invdeg[NN];
__device__ int   g_col[NE];
__device__ float g_agg[(size_t)NN * DD];
__device__ float g_h1 [(size_t)NN * DD];
__device__ float g_h2 [(size_t)NN * DD];

__device__ __forceinline__ const float* sel_in(int sel, const float* x) {
    return sel == 0 ? x : (sel == 1 ? (const float*)g_h1 : (const float*)g_h2);
}
__device__ __forceinline__ int get_src(const int* __restrict__ ei, int e) {
    return g_is64 ? ei[2 * e] : ei[e];
}
__device__ __forceinline__ int get_dst(const int* __restrict__ ei, int e) {
    return g_is64 ? ei[2 * NE + 2 * e] : ei[NE + e];
}

// Split a float pair into bf16-hi pair (packed b32) and bf16-lo residual pair.
__device__ __forceinline__ uint32_t pack_hi_lo(float a, float b, uint32_t* lo) {
    __nv_bfloat16 ha = __float2bfloat16_rn(a);
    __nv_bfloat16 hb = __float2bfloat16_rn(b);
    __nv_bfloat16 la = __float2bfloat16_rn(a - __bfloat162float(ha));
    __nv_bfloat16 lb = __float2bfloat16_rn(b - __bfloat162float(hb));
    *lo = ((uint32_t)__bfloat16_as_ushort(lb) << 16) | __bfloat16_as_ushort(la);
    return ((uint32_t)__bfloat16_as_ushort(hb) << 16) | __bfloat16_as_ushort(ha);
}

__device__ __forceinline__ void mma16816(float* d, const uint32_t* a, uint32_t b0, uint32_t b1) {
    asm volatile(
        "mma.sync.aligned.m16n8k16.row.col.f32.bf16.bf16.f32 "
        "{%0,%1,%2,%3}, {%4,%5,%6,%7}, {%8,%9}, {%0,%1,%2,%3};"
        : "+f"(d[0]), "+f"(d[1]), "+f"(d[2]), "+f"(d[3])
        : "r"(a[0]), "r"(a[1]), "r"(a[2]), "r"(a[3]), "r"(b0), "r"(b1));
}

// ---------------- dtype detection ----------------
__global__ void k_detect(const int* __restrict__ ei) {
    if (threadIdx.x == 0 && blockIdx.x == 0) {
        int acc = 0;
        for (int i = 1; i < 512; i += 2) acc |= ei[i];
        g_is64 = (acc == 0) ? 1 : 0;
    }
}

// ---------------- CSR build ----------------
__global__ void k_zero_deg() {
    int i = blockIdx.x * blockDim.x + threadIdx.x;
    if (i < NN) g_deg[i] = 0;
    if (i == 0) g_total = 0;
}
__global__ void k_hist(const int* __restrict__ ei) {
    int e = blockIdx.x * blockDim.x + threadIdx.x;
    if (e < NE) {
        int d = get_dst(ei, e);
        if ((unsigned)d < NN) atomicAdd(&g_deg[d], 1);
    }
}
__global__ __launch_bounds__(256) void k_alloc() {
    __shared__ int warp_sums[8];
    __shared__ int block_base;
    int i = blockIdx.x * 256 + threadIdx.x;
    int lane = threadIdx.x & 31;
    int wid  = threadIdx.x >> 5;
    int d = (i < NN) ? g_deg[i] : 0;
    int sc = d;
#pragma unroll
    for (int o = 1; o < 32; o <<= 1) {
        int v = __shfl_up_sync(0xffffffffu, sc, o);
        if (lane >= o) sc += v;
    }
    if (lane == 31) warp_sums[wid] = sc;
    __syncthreads();
    if (wid == 0) {
        int ws = (lane < 8) ? warp_sums[lane] : 0;
#pragma unroll
        for (int o = 1; o < 8; o <<= 1) {
            int v = __shfl_up_sync(0xffffffffu, ws, o);
            if (lane >= o) ws += v;
        }
        if (lane < 8) warp_sums[lane] = ws;
        if (lane == 7) block_base = atomicAdd(&g_total, ws);
    }
    __syncthreads();
    if (i < NN) {
        int excl = sc - d + (wid > 0 ? warp_sums[wid - 1] : 0) + block_base;
        g_off[i] = excl;
        g_cur[i] = excl;
        g_invdeg[i] = 1.0f / (float)(d > 0 ? d : 1);
    }
}
__global__ void k_fill(const int* __restrict__ ei) {
    int e = blockIdx.x * blockDim.x + threadIdx.x;
    if (e < NE) {
        int d = get_dst(ei, e);
        int s = get_src(ei, e);
        if ((unsigned)d < NN && (unsigned)s < NN) {
            int p = atomicAdd(&g_cur[d], 1);
            g_col[p] = s;
        }
    }
}

// ---------------- mean aggregation: one warp per node (round-6 body) ----------
__global__ __launch_bounds__(256) void k_agg(int sel, const float* __restrict__ x) {
    int node = (blockIdx.x * blockDim.x + threadIdx.x) >> 5;
    int lane = threadIdx.x & 31;
    if (node >= NN) return;
    const float* h = sel_in(sel, x);
    int beg = g_off[node];
    int end = beg + g_deg[node];
    float ax = 0.f, ay = 0.f, az = 0.f, aw = 0.f;
    for (int e = beg; e < end; ++e) {
        int s = g_col[e];
        float4 v = *(((const float4*)(h + (size_t)s * DD)) + lane);
        ax += v.x; ay += v.y; az += v.z; aw += v.w;
    }
    float inv = g_invdeg[node];
    float4 o = make_float4(ax * inv, ay * inv, az * inv, aw * inv);
    ((float4*)(g_agg + (size_t)node * DD))[lane] = o;
}

// ---------------- HMMA bf16-split GEMM, BK=16 double-buffered ------------------
// out = agg @ Wl^T + h @ Wr^T + b (+relu); split: AhBh + AhBl + AlBh, fp32 acc.
// 16 K-chunks of 16 (first 8: agg*Wl, last 8: h*Wr). 2 SMEM buffers, pipelined.
#define KP2 12   // b32 per SMEM row (8 data + 4 pad) -> conflict-free frags

__global__ __launch_bounds__(256) void k_gemm_mma(int in_sel, const float* __restrict__ x,
                                                  const float* __restrict__ Wl,
                                                  const float* __restrict__ bl,
                                                  const float* __restrict__ Wr,
                                                  int out_sel, float* __restrict__ ext_out,
                                                  int relu) {
    __shared__ uint32_t AsH[2][128 * KP2];
    __shared__ uint32_t AsL[2][128 * KP2];
    __shared__ uint32_t BsH[2][128 * KP2];
    __shared__ uint32_t BsL[2][128 * KP2];

    const int tid  = threadIdx.x;
    const int wid  = tid >> 5;
    const int lane = tid & 31;
    const int warpM = wid >> 1;       // 0..3
    const int warpN = wid & 1;        // 0..1
    const int blockM = blockIdx.x * 128;

    const float* A1 = sel_in(in_sel, x);
    float* outp = out_sel == 0 ? ext_out : (out_sel == 1 ? (float*)g_h1 : (float*)g_h2);

    float acc[2][8][4];
#pragma unroll
    for (int mt = 0; mt < 2; ++mt)
#pragma unroll
        for (int nt = 0; nt < 8; ++nt)
#pragma unroll
            for (int c = 0; c < 4; ++c) acc[mt][nt][c] = 0.f;

    // loader mapping: row = tid>>1 (0..127), k-half = (tid&1)*8 floats
    const int ldRow = tid >> 1;
    const int ldOf  = (tid & 1) << 3;        // float offset 0 or 8
    const int sBase = ldRow * KP2 + ((tid & 1) << 2);   // b32 offset in SMEM row
    const int aRowClamped = (blockM + ldRow < NN) ? (blockM + ldRow) : 0;

    float4 pa0, pa1, pb0, pb1;   // prefetch regs

    // chunk source helper (kc in [0,16))
#define LOAD_CHUNK(kc)  do {                                                      \
        const float* Abase = ((kc) < 8) ? (const float*)g_agg : A1;               \
        const float* Wbase = ((kc) < 8) ? Wl : Wr;                                \
        int kb = ((kc) & 7) * 16 + ldOf;                                          \
        const float* as = Abase + (size_t)aRowClamped * DD + kb;                  \
        const float* ws = Wbase + (size_t)ldRow * DD + kb;                        \
        pa0 = *(const float4*)as;  pa1 = *(const float4*)(as + 4);                \
        pb0 = *(const float4*)ws;  pb1 = *(const float4*)(ws + 4);                \
    } while (0)

#define STORE_CHUNK(buf)  do {                                                    \
        uint32_t lo;                                                              \
        uint32_t hi;                                                              \
        hi = pack_hi_lo(pa0.x, pa0.y, &lo); AsH[buf][sBase+0] = hi; AsL[buf][sBase+0] = lo; \
        hi = pack_hi_lo(pa0.z, pa0.w, &lo); AsH[buf][sBase+1] = hi; AsL[buf][sBase+1] = lo; \
        hi = pack_hi_lo(pa1.x, pa1.y, &lo); AsH[buf][sBase+2] = hi; AsL[buf][sBase+2] = lo; \
        hi = pack_hi_lo(pa1.z, pa1.w, &lo); AsH[buf][sBase+3] = hi; AsL[buf][sBase+3] = lo; \
        hi = pack_hi_lo(pb0.x, pb0.y, &lo); BsH[buf][sBase+0] = hi; BsL[buf][sBase+0] = lo; \
        hi = pack_hi_lo(pb0.z, pb0.w, &lo); BsH[buf][sBase+1] = hi; BsL[buf][sBase+1] = lo; \
        hi = pack_hi_lo(pb1.x, pb1.y, &lo); BsH[buf][sBase+2] = hi; BsL[buf][sBase+2] = lo; \
        hi = pack_hi_lo(pb1.z, pb1.w, &lo); BsH[buf][sBase+3] = hi; BsL[buf][sBase+3] = lo; \
    } while (0)

    // prologue: fill buffer 0 with chunk 0
    LOAD_CHUNK(0);
    STORE_CHUNK(0);
    __syncthreads();

    for (int kc = 0; kc < 16; ++kc) {
        const int cur = kc & 1;
        const int nxt = cur ^ 1;

        // issue global loads for next chunk early (overlap with MMAs)
        if (kc < 15) LOAD_CHUNK(kc + 1);

        // ---- compute on buf[cur] ----
        {
            uint32_t ah[2][4], al[2][4];
#pragma unroll
            for (int mt = 0; mt < 2; ++mt) {
                int row = warpM * 32 + mt * 16 + (lane >> 2);
                int base = row * KP2 + (lane & 3);
                ah[mt][0] = AsH[cur][base];
                ah[mt][1] = AsH[cur][base + 8 * KP2];
                ah[mt][2] = AsH[cur][base + 4];
                ah[mt][3] = AsH[cur][base + 8 * KP2 + 4];
                al[mt][0] = AsL[cur][base];
                al[mt][1] = AsL[cur][base + 8 * KP2];
                al[mt][2] = AsL[cur][base + 4];
                al[mt][3] = AsL[cur][base + 8 * KP2 + 4];
            }
            // product-major: same-acc MMAs are 16 apart (no RAW chains)
#pragma unroll
            for (int nt = 0; nt < 8; ++nt) {            // Ah * Bh
                int bb = (warpN * 64 + nt * 8 + (lane >> 2)) * KP2 + (lane & 3);
                uint32_t b0 = BsH[cur][bb], b1 = BsH[cur][bb + 4];
                mma16816(acc[0][nt], ah[0], b0, b1);
                mma16816(acc[1][nt], ah[1], b0, b1);
            }
#pragma unroll
            for (int nt = 0; nt < 8; ++nt) {            // Ah * Bl
                int bb = (warpN * 64 + nt * 8 + (lane >> 2)) * KP2 + (lane & 3);
                uint32_t b0 = BsL[cur][bb], b1 = BsL[cur][bb + 4];
                mma16816(acc[0][nt], ah[0], b0, b1);
                mma16816(acc[1][nt], ah[1], b0, b1);
            }
#pragma unroll
            for (int nt = 0; nt < 8; ++nt) {            // Al * Bh
                int bb = (warpN * 64 + nt * 8 + (lane >> 2)) * KP2 + (lane & 3);
                uint32_t b0 = BsH[cur][bb], b1 = BsH[cur][bb + 4];
                mma16816(acc[0][nt], al[0], b0, b1);
                mma16816(acc[1][nt], al[1], b0, b1);
            }
        }

        // pack+store next chunk into the other buffer, then one barrier
        if (kc < 15) STORE_CHUNK(nxt);
        __syncthreads();
    }

    // ---- epilogue: bias (+relu), direct float2 stores ----
#pragma unroll
    for (int nt = 0; nt < 8; ++nt) {
        int col = warpN * 64 + nt * 8 + (lane & 3) * 2;
        float2 bb = *(const float2*)(bl + col);
#pragma unroll
        for (int mt = 0; mt < 2; ++mt) {
            int row = blockM + warpM * 32 + mt * 16 + (lane >> 2);
            float* d = acc[mt][nt];
            float2 o0 = make_float2(d[0] + bb.x, d[1] + bb.y);
            float2 o1 = make_float2(d[2] + bb.x, d[3] + bb.y);
            if (relu) {
                o0.x = fmaxf(o0.x, 0.f); o0.y = fmaxf(o0.y, 0.f);
                o1.x = fmaxf(o1.x, 0.f); o1.y = fmaxf(o1.y, 0.f);
            }
            if (row < NN)     *(float2*)(outp + (size_t)row * DD + col) = o0;
            if (row + 8 < NN) *(float2*)(outp + (size_t)(row + 8) * DD + col) = o1;
        }
    }
}

// ---------------- launch (kernel launches ONLY; graph-capture safe) ----------
extern "C" void kernel_launch(void* const* d_in, const int* in_sizes, int n_in,
                              void* d_out, int out_size) {
    const float* x  = (const float*)d_in[0];
    const int*   ei = (const int*)d_in[1];
    const float* Wl1 = (const float*)d_in[2];
    const float* bl1 = (const float*)d_in[3];
    const float* Wr1 = (const float*)d_in[4];
    const float* Wl2 = (const float*)d_in[5];
    const float* bl2 = (const float*)d_in[6];
    const float* Wr2 = (const float*)d_in[7];
    const float* Wl3 = (const float*)d_in[8];
    const float* bl3 = (const float*)d_in[9];
    const float* Wr3 = (const float*)d_in[10];
    float* out = (float*)d_out;

    k_detect<<<1, 32>>>(ei);
    k_zero_deg<<<(NN + 255) / 256, 256>>>();
    k_hist<<<(NE + 255) / 256, 256>>>(ei);
    k_alloc<<<(NN + 255) / 256, 256>>>();
    k_fill<<<(NE + 255) / 256, 256>>>(ei);

    const int aggGrid  = (NN + 7) / 8;
    const int gemmGrid = (NN + 127) / 128;   // 391

    k_agg<<<aggGrid, 256>>>(0, x);
    k_gemm_mma<<<gemmGrid, 256>>>(0, x, Wl1, bl1, Wr1, 1, out, 1);
    k_agg<<<aggGrid, 256>>>(1, x);
    k_gemm_mma<<<gemmGrid, 256>>>(1, x, Wl2, bl2, Wr2, 2, out, 0);
    k_agg<<<aggGrid, 256>>>(2, x);
    k_gemm_mma<<<gemmGrid, 256>>>(2, x, Wl3, bl3, Wr3, 0, out, 0);
}